// round 1
// baseline (speedup 1.0000x reference)
#include <cuda_runtime.h>
#include <math.h>

#define N_NODES 50000
#define N_EDGES 800000
#define IN_CH 128
#define OUT_CH 32
#define HEADS 4
#define N_TYPES 4
#define N_CONF 5
#define D_OUT 128            /* HEADS*OUT_CH */
#define SEG (N_TYPES * N_NODES)   /* 200000 softmax segments */

/* ------------------------- device scratch (static, no allocation) ---------- */
__device__ float g_xt[(size_t)N_TYPES * N_NODES * D_OUT];              /* 102.4 MB */
__device__ float g_si[(size_t)N_TYPES * N_NODES * HEADS * N_CONF];     /* 16 MB */
__device__ float g_sj[(size_t)N_TYPES * N_NODES * HEADS * N_CONF];     /* 16 MB */
__device__ float g_alpha[(size_t)N_EDGES * HEADS];                     /* 12.8 MB */
__device__ int   g_cnt[SEG];
__device__ int   g_offs[SEG + 1];
__device__ int   g_cursor[SEG];
__device__ int   g_rec[N_EDGES];

/* ------------------------- f32x2 packed FMA helpers ------------------------ */
__device__ __forceinline__ unsigned long long f2dup(float v) {
    unsigned long long r;
    asm("mov.b64 %0, {%1, %1};" : "=l"(r) : "f"(v));
    return r;
}
__device__ __forceinline__ unsigned long long f2pack(float x, float y) {
    unsigned long long r;
    asm("mov.b64 %0, {%1, %2};" : "=l"(r) : "f"(x), "f"(y));
    return r;
}
__device__ __forceinline__ void ffma2(unsigned long long& c, unsigned long long a,
                                      unsigned long long b) {
    asm("fma.rn.f32x2 %0, %1, %2, %0;" : "+l"(c) : "l"(a), "l"(b));
}
__device__ __forceinline__ float2 f2unpack(unsigned long long v) {
    float2 r;
    asm("mov.b64 {%0, %1}, %2;" : "=f"(r.x), "=f"(r.y) : "l"(v));
    return r;
}

/* ============================================================================
 * K1: xt[t] = x @ W[t]  (M=50000, K=128, N=128) x 4 types, fp32 via f32x2.
 * BM=128, BN=128 (full width), BK=32, 256 threads, 8x8 per thread.
 * ==========================================================================*/
__global__ __launch_bounds__(256) void gemm_kernel(const float* __restrict__ x,
                                                   const float* __restrict__ W) {
    __shared__ float As[32][132];   /* transposed A tile, padded */
    __shared__ float Bs[32][128];

    const int t   = blockIdx.y;
    const int n0  = blockIdx.x * 128;
    const int tid = threadIdx.x;
    const int tx  = tid & 15, ty = tid >> 4;
    const float* Wt = W + (size_t)t * IN_CH * D_OUT;

    unsigned long long acc[8][4];
#pragma unroll
    for (int i = 0; i < 8; i++)
#pragma unroll
        for (int j = 0; j < 4; j++) acc[i][j] = 0ULL;

    for (int kc = 0; kc < 4; kc++) {
        /* load A tile (128 rows x 32 k), transposed into As[k][row] */
#pragma unroll
        for (int it = 0; it < 4; it++) {
            int f = tid + it * 256;
            int r = f >> 3, c4 = f & 7;
            int n = n0 + r;
            float4 v = make_float4(0.f, 0.f, 0.f, 0.f);
            if (n < N_NODES)
                v = *(const float4*)(x + (size_t)n * IN_CH + kc * 32 + c4 * 4);
            As[c4 * 4 + 0][r] = v.x;
            As[c4 * 4 + 1][r] = v.y;
            As[c4 * 4 + 2][r] = v.z;
            As[c4 * 4 + 3][r] = v.w;
        }
        /* load B tile (32 k x 128 n) */
#pragma unroll
        for (int it = 0; it < 4; it++) {
            int f = tid + it * 256;
            int kk = f >> 5, n4 = f & 31;
            float4 v = *(const float4*)(Wt + (size_t)(kc * 32 + kk) * D_OUT + n4 * 4);
            *(float4*)(&Bs[kk][n4 * 4]) = v;
        }
        __syncthreads();
#pragma unroll
        for (int kk = 0; kk < 32; kk++) {
            float4 a0 = *(const float4*)(&As[kk][ty * 8]);
            float4 a1 = *(const float4*)(&As[kk][ty * 8 + 4]);
            float4 b0 = *(const float4*)(&Bs[kk][tx * 8]);
            float4 b1 = *(const float4*)(&Bs[kk][tx * 8 + 4]);
            unsigned long long bp0 = f2pack(b0.x, b0.y);
            unsigned long long bp1 = f2pack(b0.z, b0.w);
            unsigned long long bp2 = f2pack(b1.x, b1.y);
            unsigned long long bp3 = f2pack(b1.z, b1.w);
            float av[8] = {a0.x, a0.y, a0.z, a0.w, a1.x, a1.y, a1.z, a1.w};
#pragma unroll
            for (int i = 0; i < 8; i++) {
                unsigned long long ad = f2dup(av[i]);
                ffma2(acc[i][0], ad, bp0);
                ffma2(acc[i][1], ad, bp1);
                ffma2(acc[i][2], ad, bp2);
                ffma2(acc[i][3], ad, bp3);
            }
        }
        __syncthreads();
    }
    /* store */
#pragma unroll
    for (int i = 0; i < 8; i++) {
        int n = n0 + ty * 8 + i;
        if (n >= N_NODES) break;
        float* dst = g_xt + ((size_t)t * N_NODES + n) * D_OUT + tx * 8;
        float2 p0 = f2unpack(acc[i][0]), p1 = f2unpack(acc[i][1]);
        float2 p2 = f2unpack(acc[i][2]), p3 = f2unpack(acc[i][3]);
        *(float4*)dst       = make_float4(p0.x, p0.y, p1.x, p1.y);
        *(float4*)(dst + 4) = make_float4(p2.x, p2.y, p3.x, p3.y);
    }
}

/* ============================================================================
 * K2: per-(type,node,head) endpoint scores
 *   s_i[t,n,h,k] = xt[t,n,h,:32] . att[k,h, 0:32]
 *   s_j[t,n,h,k] = xt[t,n,h,:32] . att[k,h,32:64]
 * ==========================================================================*/
__global__ __launch_bounds__(256) void score_kernel(const float* __restrict__ att) {
    __shared__ float att_s[N_CONF * HEADS * 2 * OUT_CH]; /* 1280 floats */
    for (int i = threadIdx.x; i < N_CONF * HEADS * 2 * OUT_CH; i += 256)
        att_s[i] = att[i];
    __syncthreads();

    int id = blockIdx.x * 256 + threadIdx.x;
    if (id >= SEG * HEADS) return;
    int h  = id & 3;
    int nn = id >> 2;   /* = t*N + n */

    const float4* v4 = (const float4*)(g_xt + (size_t)nn * D_OUT + h * 32);
    float si[5] = {0, 0, 0, 0, 0}, sj[5] = {0, 0, 0, 0, 0};
#pragma unroll
    for (int q = 0; q < 8; q++) {
        float4 v = v4[q];
#pragma unroll
        for (int k = 0; k < N_CONF; k++) {
            float4 ai = ((const float4*)att_s)[(k * HEADS + h) * 16 + q];
            float4 aj = ((const float4*)att_s)[(k * HEADS + h) * 16 + 8 + q];
            si[k] += v.x * ai.x + v.y * ai.y + v.z * ai.z + v.w * ai.w;
            sj[k] += v.x * aj.x + v.y * aj.y + v.z * aj.z + v.w * aj.w;
        }
    }
    float* so_i = g_si + (size_t)nn * (HEADS * N_CONF) + h * N_CONF;
    float* so_j = g_sj + (size_t)nn * (HEADS * N_CONF) + h * N_CONF;
#pragma unroll
    for (int k = 0; k < N_CONF; k++) { so_i[k] = si[k]; so_j[k] = sj[k]; }
}

/* ============================================================================
 * CSR build: histogram -> scan -> scatter, key = dst*4 + type
 * ==========================================================================*/
__global__ void hist_kernel(const int* __restrict__ ei, const int* __restrict__ et) {
    int e = blockIdx.x * 256 + threadIdx.x;
    if (e >= N_EDGES) return;
    int d = ei[N_EDGES + e];
    int t = et[e];
    atomicAdd(&g_cnt[d * 4 + t], 1);
}

__global__ __launch_bounds__(1024) void scan_kernel() {
    __shared__ int wsum[32];
    const int tid  = threadIdx.x;
    const int CH   = (SEG + 1023) / 1024; /* 196 */
    int start = tid * CH;
    int end   = min(start + CH, SEG);
    int s = 0;
    for (int i = start; i < end; i++) s += g_cnt[i];

    int lane = tid & 31, w = tid >> 5;
    int v = s;
#pragma unroll
    for (int o = 1; o < 32; o <<= 1) {
        int u = __shfl_up_sync(0xffffffffu, v, o);
        if (lane >= o) v += u;
    }
    if (lane == 31) wsum[w] = v;
    __syncthreads();
    if (w == 0) {
        int xv = wsum[lane];
#pragma unroll
        for (int o = 1; o < 32; o <<= 1) {
            int u = __shfl_up_sync(0xffffffffu, xv, o);
            if (lane >= o) xv += u;
        }
        wsum[lane] = xv;
    }
    __syncthreads();
    int base = ((w == 0) ? 0 : wsum[w - 1]) + (v - s);
    int run = base;
    for (int i = start; i < end; i++) {
        int c = g_cnt[i];
        g_offs[i]   = run;
        g_cursor[i] = run;
        run += c;
    }
    if (tid == 1023) g_offs[SEG] = run;
}

__global__ void scatter_kernel(const int* __restrict__ ei, const int* __restrict__ et) {
    int e = blockIdx.x * 256 + threadIdx.x;
    if (e >= N_EDGES) return;
    int src = ei[e];
    int d   = ei[N_EDGES + e];
    int t   = et[e];
    int pos = atomicAdd(&g_cursor[d * 4 + t], 1);
    g_rec[pos] = src;
}

/* ============================================================================
 * K4: one warp per dst node.
 *  Per (dst,type) segment: compute alpha, exact 2-pass softmax, then
 *  accumulate messages (lane = 4 output channels, coalesced xt row loads).
 *  Epilogue adds self-loop xt[0,dst] + bias.
 * ==========================================================================*/
__global__ __launch_bounds__(256) void node_kernel(const float* __restrict__ conf,
                                                   const float* __restrict__ eimp,
                                                   const float* __restrict__ bias,
                                                   float* __restrict__ out) {
    int gw   = (blockIdx.x * blockDim.x + threadIdx.x) >> 5;
    int lane = threadIdx.x & 31;
    if (gw >= N_NODES) return;
    const int dst = gw;
    const int hl  = lane >> 3; /* this lane's head (channels 4*lane..4*lane+3) */

    /* pk = softmax(confounder_probs), computed redundantly per lane (cheap) */
    float c0 = conf[0], c1 = conf[1], c2 = conf[2], c3 = conf[3], c4 = conf[4];
    float mx = fmaxf(fmaxf(fmaxf(c0, c1), fmaxf(c2, c3)), c4);
    float e0 = __expf(c0 - mx), e1 = __expf(c1 - mx), e2 = __expf(c2 - mx);
    float e3 = __expf(c3 - mx), e4 = __expf(c4 - mx);
    float inv = 1.f / (e0 + e1 + e2 + e3 + e4);
    float pk[5] = {e0 * inv, e1 * inv, e2 * inv, e3 * inv, e4 * inv};

    float4 acc = make_float4(0.f, 0.f, 0.f, 0.f);

#pragma unroll 1
    for (int t = 0; t < N_TYPES; t++) {
        int s0 = g_offs[dst * 4 + t];
        int s1 = g_offs[dst * 4 + t + 1];
        if (s0 >= s1) continue;

        /* broadcast-load s_i for (t,dst): 20 floats */
        float si[20];
        {
            const float4* sip = (const float4*)(g_si + ((size_t)t * N_NODES + dst) * 20);
#pragma unroll
            for (int q = 0; q < 5; q++) {
                float4 v = sip[q];
                si[q * 4 + 0] = v.x; si[q * 4 + 1] = v.y;
                si[q * 4 + 2] = v.z; si[q * 4 + 3] = v.w;
            }
        }

        /* pass A: alpha per edge (lanes over edges) + per-head max */
        float m[4] = {-1e30f, -1e30f, -1e30f, -1e30f};
        for (int p = s0 + lane; p < s1; p += 32) {
            int src = g_rec[p];
            const float4* sjp = (const float4*)(g_sj + ((size_t)t * N_NODES + src) * 20);
            float sj[20];
#pragma unroll
            for (int q = 0; q < 5; q++) {
                float4 v = sjp[q];
                sj[q * 4 + 0] = v.x; sj[q * 4 + 1] = v.y;
                sj[q * 4 + 2] = v.z; sj[q * 4 + 3] = v.w;
            }
            float a[4];
#pragma unroll
            for (int h = 0; h < 4; h++) {
                float ah = 0.f;
#pragma unroll
                for (int k = 0; k < N_CONF; k++) {
                    float v = si[h * 5 + k] + sj[h * 5 + k];
                    v = (v > 0.f) ? v : 0.2f * v;
                    ah += pk[k] * v;
                }
                a[h] = ah;
                m[h] = fmaxf(m[h], ah);
            }
            *(float4*)(g_alpha + (size_t)p * 4) = make_float4(a[0], a[1], a[2], a[3]);
        }
#pragma unroll
        for (int o = 16; o; o >>= 1) {
            m[0] = fmaxf(m[0], __shfl_xor_sync(0xffffffffu, m[0], o));
            m[1] = fmaxf(m[1], __shfl_xor_sync(0xffffffffu, m[1], o));
            m[2] = fmaxf(m[2], __shfl_xor_sync(0xffffffffu, m[2], o));
            m[3] = fmaxf(m[3], __shfl_xor_sync(0xffffffffu, m[3], o));
        }

        /* pass B: exp-sum */
        float d4[4] = {0.f, 0.f, 0.f, 0.f};
        for (int p = s0 + lane; p < s1; p += 32) {
            float4 av = *(const float4*)(g_alpha + (size_t)p * 4);
            d4[0] += __expf(av.x - m[0]);
            d4[1] += __expf(av.y - m[1]);
            d4[2] += __expf(av.z - m[2]);
            d4[3] += __expf(av.w - m[3]);
        }
#pragma unroll
        for (int o = 16; o; o >>= 1) {
            d4[0] += __shfl_xor_sync(0xffffffffu, d4[0], o);
            d4[1] += __shfl_xor_sync(0xffffffffu, d4[1], o);
            d4[2] += __shfl_xor_sync(0xffffffffu, d4[2], o);
            d4[3] += __shfl_xor_sync(0xffffffffu, d4[3], o);
        }
        __syncwarp();

        /* pass C: accumulate, serial over edges, lanes over channels.
           2-deep software pipeline on the index/alpha loads. */
        float wscale = eimp[t] / d4[hl];
        float mh     = m[hl];
        int   p      = s0;
        int   src_n  = g_rec[p];
        float a_n    = g_alpha[(size_t)p * 4 + hl];
        while (p < s1) {
            int   src_c = src_n;
            float a_c   = a_n;
            int   pn    = p + 1;
            if (pn < s1) {
                src_n = g_rec[pn];
                a_n   = g_alpha[(size_t)pn * 4 + hl];
            }
            float4 xv = ((const float4*)(g_xt + (((size_t)t * N_NODES + src_c) << 7)))[lane];
            float w = __expf(a_c - mh) * wscale;
            acc.x += w * xv.x;
            acc.y += w * xv.y;
            acc.z += w * xv.z;
            acc.w += w * xv.w;
            p = pn;
        }
    }

    /* epilogue: + x @ W[0] (= xt[0,dst]) + bias */
    float4 self = ((const float4*)(g_xt + ((size_t)dst << 7)))[lane];
    float4 bb   = ((const float4*)bias)[lane];
    float4 o;
    o.x = acc.x + self.x + bb.x;
    o.y = acc.y + self.y + bb.y;
    o.z = acc.z + self.z + bb.z;
    o.w = acc.w + self.w + bb.w;
    ((float4*)(out + (size_t)dst * D_OUT))[lane] = o;
}

/* ============================================================================ */
extern "C" void kernel_launch(void* const* d_in, const int* in_sizes, int n_in,
                              void* d_out, int out_size) {
    const float* x    = (const float*)d_in[0];
    const int*   ei   = (const int*)d_in[1];
    const int*   et   = (const int*)d_in[2];
    const float* W    = (const float*)d_in[3];
    const float* att  = (const float*)d_in[4];
    const float* conf = (const float*)d_in[5];
    const float* eimp = (const float*)d_in[6];
    const float* bias = (const float*)d_in[7];
    float*       out  = (float*)d_out;

    void* cntp = nullptr;
    cudaGetSymbolAddress(&cntp, g_cnt);
    cudaMemsetAsync(cntp, 0, SEG * sizeof(int));

    dim3 gg((N_NODES + 127) / 128, N_TYPES);
    gemm_kernel<<<gg, 256>>>(x, W);
    score_kernel<<<(SEG * HEADS + 255) / 256, 256>>>(att);
    hist_kernel<<<(N_EDGES + 255) / 256, 256>>>(ei, et);
    scan_kernel<<<1, 1024>>>();
    scatter_kernel<<<(N_EDGES + 255) / 256, 256>>>(ei, et);
    node_kernel<<<(N_NODES * 32 + 255) / 256, 256>>>(conf, eimp, bias, out);
}

// round 2
// speedup vs baseline: 1.6578x; 1.6578x over previous
#include <cuda_runtime.h>
#include <math.h>

#define N_NODES 50000
#define N_EDGES 800000
#define IN_CH 128
#define OUT_CH 32
#define HEADS 4
#define N_TYPES 4
#define N_CONF 5
#define D_OUT 128            /* HEADS*OUT_CH */
#define SEG (N_TYPES * N_NODES)   /* 200000 softmax segments */
#define SCAN_BLOCKS ((SEG + 1023) / 1024)   /* 196 */

/* ------------------------- device scratch (static, no allocation) ---------- */
__device__ float g_xt[(size_t)N_TYPES * N_NODES * D_OUT];              /* 102.4 MB */
__device__ float g_si[(size_t)N_TYPES * N_NODES * HEADS * N_CONF];     /* 16 MB */
__device__ float g_sj[(size_t)N_TYPES * N_NODES * HEADS * N_CONF];     /* 16 MB */
__device__ float g_alpha[(size_t)N_EDGES * HEADS];                     /* 12.8 MB */
__device__ int   g_cnt[SEG];
__device__ int   g_offs[SEG + 1];
__device__ int   g_cursor[SEG];
__device__ int   g_rec[N_EDGES];
__device__ int   g_bsum[SCAN_BLOCKS];

/* ------------------------- f32x2 packed FMA helpers ------------------------ */
__device__ __forceinline__ unsigned long long f2dup(float v) {
    unsigned long long r;
    asm("mov.b64 %0, {%1, %1};" : "=l"(r) : "f"(v));
    return r;
}
__device__ __forceinline__ unsigned long long f2pack(float x, float y) {
    unsigned long long r;
    asm("mov.b64 %0, {%1, %2};" : "=l"(r) : "f"(x), "f"(y));
    return r;
}
__device__ __forceinline__ void ffma2(unsigned long long& c, unsigned long long a,
                                      unsigned long long b) {
    asm("fma.rn.f32x2 %0, %1, %2, %0;" : "+l"(c) : "l"(a), "l"(b));
}
__device__ __forceinline__ float2 f2unpack(unsigned long long v) {
    float2 r;
    asm("mov.b64 {%0, %1}, %2;" : "=f"(r.x), "=f"(r.y) : "l"(v));
    return r;
}

/* ============================================================================
 * K1: xt[t] = x @ W[t]  (M=50000, K=128, N=128) x 4 types, fp32 via f32x2.
 * BM=128, BN=128 (full width), BK=32, 256 threads, 8x8 per thread.
 * ==========================================================================*/
__global__ __launch_bounds__(256) void gemm_kernel(const float* __restrict__ x,
                                                   const float* __restrict__ W) {
    __shared__ float As[32][132];   /* transposed A tile, padded */
    __shared__ float Bs[32][128];

    const int t   = blockIdx.y;
    const int n0  = blockIdx.x * 128;
    const int tid = threadIdx.x;
    const int tx  = tid & 15, ty = tid >> 4;
    const float* Wt = W + (size_t)t * IN_CH * D_OUT;

    unsigned long long acc[8][4];
#pragma unroll
    for (int i = 0; i < 8; i++)
#pragma unroll
        for (int j = 0; j < 4; j++) acc[i][j] = 0ULL;

    for (int kc = 0; kc < 4; kc++) {
        /* load A tile (128 rows x 32 k), transposed into As[k][row] */
#pragma unroll
        for (int it = 0; it < 4; it++) {
            int f = tid + it * 256;
            int r = f >> 3, c4 = f & 7;
            int n = n0 + r;
            float4 v = make_float4(0.f, 0.f, 0.f, 0.f);
            if (n < N_NODES)
                v = *(const float4*)(x + (size_t)n * IN_CH + kc * 32 + c4 * 4);
            As[c4 * 4 + 0][r] = v.x;
            As[c4 * 4 + 1][r] = v.y;
            As[c4 * 4 + 2][r] = v.z;
            As[c4 * 4 + 3][r] = v.w;
        }
        /* load B tile (32 k x 128 n) */
#pragma unroll
        for (int it = 0; it < 4; it++) {
            int f = tid + it * 256;
            int kk = f >> 5, n4 = f & 31;
            float4 v = *(const float4*)(Wt + (size_t)(kc * 32 + kk) * D_OUT + n4 * 4);
            *(float4*)(&Bs[kk][n4 * 4]) = v;
        }
        __syncthreads();
#pragma unroll
        for (int kk = 0; kk < 32; kk++) {
            float4 a0 = *(const float4*)(&As[kk][ty * 8]);
            float4 a1 = *(const float4*)(&As[kk][ty * 8 + 4]);
            float4 b0 = *(const float4*)(&Bs[kk][tx * 8]);
            float4 b1 = *(const float4*)(&Bs[kk][tx * 8 + 4]);
            unsigned long long bp0 = f2pack(b0.x, b0.y);
            unsigned long long bp1 = f2pack(b0.z, b0.w);
            unsigned long long bp2 = f2pack(b1.x, b1.y);
            unsigned long long bp3 = f2pack(b1.z, b1.w);
            float av[8] = {a0.x, a0.y, a0.z, a0.w, a1.x, a1.y, a1.z, a1.w};
#pragma unroll
            for (int i = 0; i < 8; i++) {
                unsigned long long ad = f2dup(av[i]);
                ffma2(acc[i][0], ad, bp0);
                ffma2(acc[i][1], ad, bp1);
                ffma2(acc[i][2], ad, bp2);
                ffma2(acc[i][3], ad, bp3);
            }
        }
        __syncthreads();
    }
    /* store */
#pragma unroll
    for (int i = 0; i < 8; i++) {
        int n = n0 + ty * 8 + i;
        if (n >= N_NODES) break;
        float* dst = g_xt + ((size_t)t * N_NODES + n) * D_OUT + tx * 8;
        float2 p0 = f2unpack(acc[i][0]), p1 = f2unpack(acc[i][1]);
        float2 p2 = f2unpack(acc[i][2]), p3 = f2unpack(acc[i][3]);
        *(float4*)dst       = make_float4(p0.x, p0.y, p1.x, p1.y);
        *(float4*)(dst + 4) = make_float4(p2.x, p2.y, p3.x, p3.y);
    }
}

/* ============================================================================
 * K2: per-(type,node,head) endpoint scores
 * ==========================================================================*/
__global__ __launch_bounds__(256) void score_kernel(const float* __restrict__ att) {
    __shared__ float att_s[N_CONF * HEADS * 2 * OUT_CH]; /* 1280 floats */
    for (int i = threadIdx.x; i < N_CONF * HEADS * 2 * OUT_CH; i += 256)
        att_s[i] = att[i];
    __syncthreads();

    int id = blockIdx.x * 256 + threadIdx.x;
    if (id >= SEG * HEADS) return;
    int h  = id & 3;
    int nn = id >> 2;   /* = t*N + n */

    const float4* v4 = (const float4*)(g_xt + (size_t)nn * D_OUT + h * 32);
    float si[5] = {0, 0, 0, 0, 0}, sj[5] = {0, 0, 0, 0, 0};
#pragma unroll
    for (int q = 0; q < 8; q++) {
        float4 v = v4[q];
#pragma unroll
        for (int k = 0; k < N_CONF; k++) {
            float4 ai = ((const float4*)att_s)[(k * HEADS + h) * 16 + q];
            float4 aj = ((const float4*)att_s)[(k * HEADS + h) * 16 + 8 + q];
            si[k] += v.x * ai.x + v.y * ai.y + v.z * ai.z + v.w * ai.w;
            sj[k] += v.x * aj.x + v.y * aj.y + v.z * aj.z + v.w * aj.w;
        }
    }
    float* so_i = g_si + (size_t)nn * (HEADS * N_CONF) + h * N_CONF;
    float* so_j = g_sj + (size_t)nn * (HEADS * N_CONF) + h * N_CONF;
#pragma unroll
    for (int k = 0; k < N_CONF; k++) { so_i[k] = si[k]; so_j[k] = sj[k]; }
}

/* ============================================================================
 * CSR build: histogram -> 3-phase multi-block scan -> scatter
 * key = dst*4 + type
 * ==========================================================================*/
__global__ void hist_kernel(const int* __restrict__ ei, const int* __restrict__ et) {
    int e = blockIdx.x * 256 + threadIdx.x;
    if (e >= N_EDGES) return;
    int d = ei[N_EDGES + e];
    int t = et[e];
    atomicAdd(&g_cnt[d * 4 + t], 1);
}

/* block-wide inclusive scan of per-thread value v; returns inclusive prefix,
   and writes the block total to *tot (valid in all threads). */
__device__ __forceinline__ int block_scan_1024(int v, int* smem32, int* tot) {
    int lane = threadIdx.x & 31, w = threadIdx.x >> 5;
    int inc = v;
#pragma unroll
    for (int o = 1; o < 32; o <<= 1) {
        int u = __shfl_up_sync(0xffffffffu, inc, o);
        if (lane >= o) inc += u;
    }
    if (lane == 31) smem32[w] = inc;
    __syncthreads();
    if (w == 0) {
        int ws = smem32[lane];
#pragma unroll
        for (int o = 1; o < 32; o <<= 1) {
            int u = __shfl_up_sync(0xffffffffu, ws, o);
            if (lane >= o) ws += u;
        }
        smem32[lane] = ws;
    }
    __syncthreads();
    int base = (w == 0) ? 0 : smem32[w - 1];
    *tot = smem32[31];
    return inc + base;
}

__global__ __launch_bounds__(1024) void scan_phase1() {
    int idx = blockIdx.x * 1024 + threadIdx.x;
    int v = (idx < SEG) ? g_cnt[idx] : 0;
    __shared__ int smem32[32];
    int tot;
    block_scan_1024(v, smem32, &tot);
    if (threadIdx.x == 0) g_bsum[blockIdx.x] = tot;
}

__global__ __launch_bounds__(256) void scan_phase2() {
    /* exclusive scan of SCAN_BLOCKS(=196) block sums, single block */
    __shared__ int smem32[32];
    int v = (threadIdx.x < SCAN_BLOCKS) ? g_bsum[threadIdx.x] : 0;
    int lane = threadIdx.x & 31, w = threadIdx.x >> 5;
    int inc = v;
#pragma unroll
    for (int o = 1; o < 32; o <<= 1) {
        int u = __shfl_up_sync(0xffffffffu, inc, o);
        if (lane >= o) inc += u;
    }
    if (lane == 31) smem32[w] = inc;
    __syncthreads();
    if (w == 0) {
        int ws = (lane < 8) ? smem32[lane] : 0;
#pragma unroll
        for (int o = 1; o < 8; o <<= 1) {
            int u = __shfl_up_sync(0xffffffffu, ws, o);
            if (lane >= o) ws += u;
        }
        if (lane < 8) smem32[lane] = ws;
    }
    __syncthreads();
    int base = (w == 0) ? 0 : smem32[w - 1];
    int excl = inc + base - v;
    if (threadIdx.x < SCAN_BLOCKS) g_bsum[threadIdx.x] = excl;
}

__global__ __launch_bounds__(1024) void scan_phase3() {
    int idx = blockIdx.x * 1024 + threadIdx.x;
    int v = (idx < SEG) ? g_cnt[idx] : 0;
    __shared__ int smem32[32];
    int tot;
    int inc = block_scan_1024(v, smem32, &tot);
    int excl = inc - v + g_bsum[blockIdx.x];
    if (idx < SEG) {
        g_offs[idx]   = excl;
        g_cursor[idx] = excl;
        if (idx == SEG - 1) g_offs[SEG] = excl + v;
    }
}

__global__ void scatter_kernel(const int* __restrict__ ei, const int* __restrict__ et) {
    int e = blockIdx.x * 256 + threadIdx.x;
    if (e >= N_EDGES) return;
    int src = ei[e];
    int d   = ei[N_EDGES + e];
    int t   = et[e];
    int pos = atomicAdd(&g_cursor[d * 4 + t], 1);
    g_rec[pos] = src;
}

/* ============================================================================
 * K4: one warp per dst node.
 * ==========================================================================*/
__global__ __launch_bounds__(256) void node_kernel(const float* __restrict__ conf,
                                                   const float* __restrict__ eimp,
                                                   const float* __restrict__ bias,
                                                   float* __restrict__ out) {
    int gw   = (blockIdx.x * blockDim.x + threadIdx.x) >> 5;
    int lane = threadIdx.x & 31;
    if (gw >= N_NODES) return;
    const int dst = gw;
    const int hl  = lane >> 3; /* this lane's head (channels 4*lane..4*lane+3) */

    /* pk = softmax(confounder_probs), computed redundantly per lane (cheap) */
    float c0 = conf[0], c1 = conf[1], c2 = conf[2], c3 = conf[3], c4 = conf[4];
    float mx = fmaxf(fmaxf(fmaxf(c0, c1), fmaxf(c2, c3)), c4);
    float e0 = __expf(c0 - mx), e1 = __expf(c1 - mx), e2 = __expf(c2 - mx);
    float e3 = __expf(c3 - mx), e4 = __expf(c4 - mx);
    float inv = 1.f / (e0 + e1 + e2 + e3 + e4);
    float pk[5] = {e0 * inv, e1 * inv, e2 * inv, e3 * inv, e4 * inv};

    float4 acc = make_float4(0.f, 0.f, 0.f, 0.f);

#pragma unroll 1
    for (int t = 0; t < N_TYPES; t++) {
        int s0 = g_offs[dst * 4 + t];
        int s1 = g_offs[dst * 4 + t + 1];
        if (s0 >= s1) continue;

        /* broadcast-load s_i for (t,dst): 20 floats */
        float si[20];
        {
            const float4* sip = (const float4*)(g_si + ((size_t)t * N_NODES + dst) * 20);
#pragma unroll
            for (int q = 0; q < 5; q++) {
                float4 v = sip[q];
                si[q * 4 + 0] = v.x; si[q * 4 + 1] = v.y;
                si[q * 4 + 2] = v.z; si[q * 4 + 3] = v.w;
            }
        }

        /* pass A: alpha per edge (lanes over edges) + per-head max */
        float m[4] = {-1e30f, -1e30f, -1e30f, -1e30f};
        for (int p = s0 + lane; p < s1; p += 32) {
            int src = g_rec[p];
            const float4* sjp = (const float4*)(g_sj + ((size_t)t * N_NODES + src) * 20);
            float sj[20];
#pragma unroll
            for (int q = 0; q < 5; q++) {
                float4 v = sjp[q];
                sj[q * 4 + 0] = v.x; sj[q * 4 + 1] = v.y;
                sj[q * 4 + 2] = v.z; sj[q * 4 + 3] = v.w;
            }
            float a[4];
#pragma unroll
            for (int h = 0; h < 4; h++) {
                float ah = 0.f;
#pragma unroll
                for (int k = 0; k < N_CONF; k++) {
                    float v = si[h * 5 + k] + sj[h * 5 + k];
                    v = (v > 0.f) ? v : 0.2f * v;
                    ah += pk[k] * v;
                }
                a[h] = ah;
                m[h] = fmaxf(m[h], ah);
            }
            *(float4*)(g_alpha + (size_t)p * 4) = make_float4(a[0], a[1], a[2], a[3]);
        }
#pragma unroll
        for (int o = 16; o; o >>= 1) {
            m[0] = fmaxf(m[0], __shfl_xor_sync(0xffffffffu, m[0], o));
            m[1] = fmaxf(m[1], __shfl_xor_sync(0xffffffffu, m[1], o));
            m[2] = fmaxf(m[2], __shfl_xor_sync(0xffffffffu, m[2], o));
            m[3] = fmaxf(m[3], __shfl_xor_sync(0xffffffffu, m[3], o));
        }

        /* pass B: exp-sum */
        float d4[4] = {0.f, 0.f, 0.f, 0.f};
        for (int p = s0 + lane; p < s1; p += 32) {
            float4 av = *(const float4*)(g_alpha + (size_t)p * 4);
            d4[0] += __expf(av.x - m[0]);
            d4[1] += __expf(av.y - m[1]);
            d4[2] += __expf(av.z - m[2]);
            d4[3] += __expf(av.w - m[3]);
        }
#pragma unroll
        for (int o = 16; o; o >>= 1) {
            d4[0] += __shfl_xor_sync(0xffffffffu, d4[0], o);
            d4[1] += __shfl_xor_sync(0xffffffffu, d4[1], o);
            d4[2] += __shfl_xor_sync(0xffffffffu, d4[2], o);
            d4[3] += __shfl_xor_sync(0xffffffffu, d4[3], o);
        }
        __syncwarp();

        /* pass C: accumulate, serial over edges, lanes over channels.
           2-deep software pipeline on the index/alpha loads. */
        float wscale = eimp[t] / d4[hl];
        float mh     = m[hl];
        int   p      = s0;
        int   src_n  = g_rec[p];
        float a_n    = g_alpha[(size_t)p * 4 + hl];
        while (p < s1) {
            int   src_c = src_n;
            float a_c   = a_n;
            int   pn    = p + 1;
            if (pn < s1) {
                src_n = g_rec[pn];
                a_n   = g_alpha[(size_t)pn * 4 + hl];
            }
            float4 xv = ((const float4*)(g_xt + (((size_t)t * N_NODES + src_c) << 7)))[lane];
            float w = __expf(a_c - mh) * wscale;
            acc.x += w * xv.x;
            acc.y += w * xv.y;
            acc.z += w * xv.z;
            acc.w += w * xv.w;
            p = pn;
        }
    }

    /* epilogue: + x @ W[0] (= xt[0,dst]) + bias */
    float4 self = ((const float4*)(g_xt + ((size_t)dst << 7)))[lane];
    float4 bb   = ((const float4*)bias)[lane];
    float4 o;
    o.x = acc.x + self.x + bb.x;
    o.y = acc.y + self.y + bb.y;
    o.z = acc.z + self.z + bb.z;
    o.w = acc.w + self.w + bb.w;
    ((float4*)(out + (size_t)dst * D_OUT))[lane] = o;
}

/* ============================================================================ */
extern "C" void kernel_launch(void* const* d_in, const int* in_sizes, int n_in,
                              void* d_out, int out_size) {
    const float* x    = (const float*)d_in[0];
    const int*   ei   = (const int*)d_in[1];
    const int*   et   = (const int*)d_in[2];
    const float* W    = (const float*)d_in[3];
    const float* att  = (const float*)d_in[4];
    const float* conf = (const float*)d_in[5];
    const float* eimp = (const float*)d_in[6];
    const float* bias = (const float*)d_in[7];
    float*       out  = (float*)d_out;

    void* cntp = nullptr;
    cudaGetSymbolAddress(&cntp, g_cnt);
    cudaMemsetAsync(cntp, 0, SEG * sizeof(int));

    dim3 gg((N_NODES + 127) / 128, N_TYPES);
    gemm_kernel<<<gg, 256>>>(x, W);
    score_kernel<<<(SEG * HEADS + 255) / 256, 256>>>(att);
    hist_kernel<<<(N_EDGES + 255) / 256, 256>>>(ei, et);
    scan_phase1<<<SCAN_BLOCKS, 1024>>>();
    scan_phase2<<<1, 256>>>();
    scan_phase3<<<SCAN_BLOCKS, 1024>>>();
    scatter_kernel<<<(N_EDGES + 255) / 256, 256>>>(ei, et);
    node_kernel<<<(N_NODES * 32 + 255) / 256, 256>>>(conf, eimp, bias, out);
}